// round 9
// baseline (speedup 1.0000x reference)
#include <cuda_runtime.h>

#define T_DIM 512
#define TPB   256
#define N_STEPS 5

__device__ __forceinline__ float sgnf(float x) {
    return (x > 0.0f) ? 1.0f : ((x < 0.0f) ? -1.0f : 0.0f);
}

__device__ __forceinline__ float rescale_f(float x) {
    const float EPS = 1e-3f;
    return sgnf(x) * (sqrtf(fabsf(x) + 1.0f) - 1.0f) + EPS * x;
}

__device__ __forceinline__ float inv_rescale_f(float x) {
    const float EPS = 1e-3f;
    float sqrt_arg = 1.0f + 4.0f * EPS * (fabsf(x) + 1.0f + EPS);
    float r = (sqrtf(sqrt_arg) - 1.0f) / (2.0f * EPS);
    return sgnf(x) * (r * r - 1.0f);
}

__global__ __launch_bounds__(TPB, 6)
void nstep_qloss_kernel(const float* __restrict__ cq,
                        const float* __restrict__ nq,
                        const float* __restrict__ logp,
                        const float* __restrict__ rw,
                        const float* __restrict__ done,
                        const float* __restrict__ mask,
                        float* __restrict__ out)
{
    // Only A is staged in shared: A[t] = m*reward + gamma*inv_qw*(md*logp/3)
    __shared__ float4 s_A[T_DIM + N_STEPS - 1];

    const float GAMMA  = 0.997f;
    const float GAMMA2 = 0.997f * 0.997f;
    const float GAMMA3 = GAMMA2 * 0.997f;
    const float GAMMA4 = GAMMA3 * 0.997f;
    const float GAMMA5 = GAMMA4 * 0.997f;
    const float LN_GAMMA = -0.003004509021390342f; // ln(0.997)

    const int b   = blockIdx.x;
    const int l   = threadIdx.x;
    const int t0  = 2 * l;
    const int row = b * T_DIM;
    const int bt0 = row + t0;              // float4-unit index for Q=4 streams
    const int sc  = b * TPB + l;           // float2-unit index for scalar streams

    // gathered indices (clamped at row end; last 2 threads broadcast-read 511)
    const int idx0 = min(T_DIM - 1, t0 + 4);
    const int idx1 = min(T_DIM - 1, t0 + 5);

    // ---- hoisted global loads (max MLP) ----
    float4 c0 = ((const float4*)cq)[bt0];
    float4 c1 = ((const float4*)cq)[bt0 + 1];
    float2 m2 = ((const float2*)mask)[sc];
    float2 d2 = ((const float2*)done)[sc];
    float2 p2 = ((const float2*)logp)[sc];
    float4 r0 = ((const float4*)rw)[bt0];
    float4 r1 = ((const float4*)rw)[bt0 + 1];
    // shifted (gathered) streams loaded directly from global — no staging
    float  mi0 = mask[row + idx0];
    float  mi1 = mask[row + idx1];
    float  di0 = done[row + idx0];
    float  di1 = done[row + idx1];
    float4 n0  = ((const float4*)nq)[row + idx0];
    float4 n1  = ((const float4*)nq)[row + idx1];

    const float md0 = m2.x * (1.0f - d2.x);
    const float md1 = m2.y * (1.0f - d2.y);
    const float lb0 = (GAMMA / 3.0f) * md0 * p2.x;   // per-lane *inv_qw = [1,2,-,0.5]
    const float lb1 = (GAMMA / 3.0f) * md1 * p2.y;

    float4 a0, a1;
    a0.x = fmaf(m2.x, r0.x, lb0);
    a0.y = fmaf(m2.x, r0.y, 2.0f * lb0);
    a0.z = 0.0f;
    a0.w = fmaf(m2.x, r0.w, 0.5f * lb0);
    a1.x = fmaf(m2.y, r1.x, lb1);
    a1.y = fmaf(m2.y, r1.y, 2.0f * lb1);
    a1.z = 0.0f;
    a1.w = fmaf(m2.y, r1.w, 0.5f * lb1);
    s_A[t0]     = a0;
    s_A[t0 + 1] = a1;
    if (l < 2) {
        s_A[T_DIM + 2 * l]     = make_float4(0.f, 0.f, 0.f, 0.f);
        s_A[T_DIM + 2 * l + 1] = make_float4(0.f, 0.f, 0.f, 0.f);
    }

    // gathered next-q term computed directly in registers
    const float mdi0 = mi0 * (1.0f - di0);
    const float mdi1 = mi1 * (1.0f - di1);
    float v0x = mdi0 * inv_rescale_f(n0.x);
    float v0y = mdi0 * inv_rescale_f(n0.y);
    float v0w = mdi0 * inv_rescale_f(n0.w);
    float v1x = mdi1 * inv_rescale_f(n1.x);
    float v1y = mdi1 * inv_rescale_f(n1.y);
    float v1w = mdi1 * inv_rescale_f(n1.w);

    __syncthreads();

    // window values A[t0+2 .. t0+5] from shared; A[t0], A[t0+1] in regs
    float4 A2 = s_A[t0 + 2];
    float4 A3 = s_A[t0 + 3];
    float4 A4 = s_A[t0 + 4];
    float4 A5 = s_A[t0 + 5];

    // rs1 = sum_{n=0..4} gamma^n A[t0+1+n]
    float rs1x = fmaf(GAMMA4, A5.x, fmaf(GAMMA3, A4.x, fmaf(GAMMA2, A3.x, fmaf(GAMMA, A2.x, a1.x))));
    float rs1y = fmaf(GAMMA4, A5.y, fmaf(GAMMA3, A4.y, fmaf(GAMMA2, A3.y, fmaf(GAMMA, A2.y, a1.y))));
    float rs1w = fmaf(GAMMA4, A5.w, fmaf(GAMMA3, A4.w, fmaf(GAMMA2, A3.w, fmaf(GAMMA, A2.w, a1.w))));
    // rs0 = A[t0] + gamma*rs1 - gamma^5 * A[t0+5]
    float rs0x = fmaf(GAMMA, rs1x, fmaf(-GAMMA5, A5.x, a0.x));
    float rs0y = fmaf(GAMMA, rs1y, fmaf(-GAMMA5, A5.y, a0.y));
    float rs0w = fmaf(GAMMA, rs1w, fmaf(-GAMMA5, A5.w, a0.w));

    const float gi0 = expf((float)idx0 * LN_GAMMA);          // gamma^idx (absolute)
    const float gi1 = (idx1 == idx0) ? gi0 : gi0 * GAMMA;

    // Q_WEIGHTS = [1, 0.5, 0, 2]
    float e0x = c0.x - rescale_f(fmaf(gi0, v0x, rs0x));
    float e0y = c0.y - rescale_f(fmaf(gi0, v0y, rs0y));
    float e0w = c0.w - rescale_f(fmaf(gi0, v0w, rs0w));
    float e1x = c1.x - rescale_f(fmaf(gi1, v1x, rs1x));
    float e1y = c1.y - rescale_f(fmaf(gi1, v1y, rs1y));
    float e1w = c1.w - rescale_f(fmaf(gi1, v1w, rs1w));

    float4 o0, o1;
    o0.x = 0.5f  * m2.x * e0x * e0x;
    o0.y = 0.25f * m2.x * e0y * e0y;
    o0.z = 0.0f;
    o0.w = m2.x * e0w * e0w;
    o1.x = 0.5f  * m2.y * e1x * e1x;
    o1.y = 0.25f * m2.y * e1y * e1y;
    o1.z = 0.0f;
    o1.w = m2.y * e1w * e1w;

    ((float4*)out)[bt0]     = o0;
    ((float4*)out)[bt0 + 1] = o1;
}

extern "C" void kernel_launch(void* const* d_in, const int* in_sizes, int n_in,
                              void* d_out, int out_size)
{
    // metadata order: current_q_value, next_q_value, log_p, reward, is_done, mask
    const float* cq   = (const float*)d_in[0];
    const float* nq   = (const float*)d_in[1];
    const float* logp = (const float*)d_in[2];
    const float* rw   = (const float*)d_in[3];
    const float* done = (const float*)d_in[4];
    const float* mask = (const float*)d_in[5];
    float* out = (float*)d_out;

    int B = in_sizes[2] / T_DIM;   // log_p has B*T elements
    nstep_qloss_kernel<<<B, TPB>>>(cq, nq, logp, rw, done, mask, out);
}

// round 10
// speedup vs baseline: 1.0304x; 1.0304x over previous
#include <cuda_runtime.h>

#define T_DIM 512
#define TPB   256
#define N_STEPS 5

__device__ __forceinline__ float sgnf(float x) {
    return (x > 0.0f) ? 1.0f : ((x < 0.0f) ? -1.0f : 0.0f);
}

__device__ __forceinline__ float rescale_f(float x) {
    const float EPS = 1e-3f;
    return sgnf(x) * (sqrtf(fabsf(x) + 1.0f) - 1.0f) + EPS * x;
}

__device__ __forceinline__ float inv_rescale_f(float x) {
    const float EPS = 1e-3f;
    float sqrt_arg = 1.0f + 4.0f * EPS * (fabsf(x) + 1.0f + EPS);
    float r = (sqrtf(sqrt_arg) - 1.0f) / (2.0f * EPS);
    return sgnf(x) * (r * r - 1.0f);
}

// Build A[t] = (m*r + gamma*inv_qw*(md*lp/3)) for lanes that cross the warp
// boundary; zero past the row end (matches zero-padding semantics).
__device__ __forceinline__ void buildA(const float* __restrict__ mask,
                                       const float* __restrict__ done,
                                       const float* __restrict__ logp,
                                       const float4* __restrict__ rw4,
                                       int row, int t,
                                       float& ax, float& ay, float& aw)
{
    const float GAMMA = 0.997f;
    if (t >= T_DIM) { ax = ay = aw = 0.0f; return; }
    float  m = mask[row + t];
    float  d = done[row + t];
    float  p = logp[row + t];
    float4 r = rw4[row + t];
    float md = m * (1.0f - d);
    float lb = (GAMMA / 3.0f) * md * p;
    ax = fmaf(m, r.x, lb);
    ay = fmaf(m, r.y, 2.0f * lb);
    aw = fmaf(m, r.w, 0.5f * lb);
}

__global__ __launch_bounds__(TPB)
void nstep_qloss_kernel(const float* __restrict__ cq,
                        const float* __restrict__ nq,
                        const float* __restrict__ logp,
                        const float* __restrict__ rw,
                        const float* __restrict__ done,
                        const float* __restrict__ mask,
                        float* __restrict__ out)
{
    const float GAMMA  = 0.997f;
    const float GAMMA2 = 0.997f * 0.997f;
    const float GAMMA3 = GAMMA2 * 0.997f;
    const float GAMMA4 = GAMMA3 * 0.997f;
    const float GAMMA5 = GAMMA4 * 0.997f;
    const float LN_GAMMA = -0.003004509021390342f; // ln(0.997)

    const int b    = blockIdx.x;
    const int l    = threadIdx.x;
    const int lane = l & 31;
    const int t0   = 2 * l;
    const int row  = b * T_DIM;
    const int bt0  = row + t0;             // float4-unit index for Q=4 streams
    const int sc   = b * TPB + l;          // float2-unit index for scalar streams

    const float4* rw4 = (const float4*)rw;

    // gathered indices (clamped at row end)
    const int idx0 = min(T_DIM - 1, t0 + 4);
    const int idx1 = min(T_DIM - 1, t0 + 5);

    // ---- hoisted global loads ----
    float4 c0 = ((const float4*)cq)[bt0];
    float4 c1 = ((const float4*)cq)[bt0 + 1];
    float2 m2 = ((const float2*)mask)[sc];
    float2 d2 = ((const float2*)done)[sc];
    float2 p2 = ((const float2*)logp)[sc];
    float4 r0 = rw4[bt0];
    float4 r1 = rw4[bt0 + 1];
    float  mi0 = mask[row + idx0];
    float  mi1 = mask[row + idx1];
    float  di0 = done[row + idx0];
    float  di1 = done[row + idx1];
    float4 n0  = ((const float4*)nq)[row + idx0];
    float4 n1  = ((const float4*)nq)[row + idx1];

    const float md0 = m2.x * (1.0f - d2.x);
    const float md1 = m2.y * (1.0f - d2.y);
    const float lb0 = (GAMMA / 3.0f) * md0 * p2.x;   // per-lane *inv_qw = [1,2,-,0.5]
    const float lb1 = (GAMMA / 3.0f) * md1 * p2.y;

    // own A values (x, y, w components; z lane dead)
    float a0x = fmaf(m2.x, r0.x, lb0);
    float a0y = fmaf(m2.x, r0.y, 2.0f * lb0);
    float a0w = fmaf(m2.x, r0.w, 0.5f * lb0);
    float a1x = fmaf(m2.y, r1.x, lb1);
    float a1y = fmaf(m2.y, r1.y, 2.0f * lb1);
    float a1w = fmaf(m2.y, r1.w, 0.5f * lb1);

    // gathered next-q term
    const float mdi0 = mi0 * (1.0f - di0);
    const float mdi1 = mi1 * (1.0f - di1);
    float v0x = mdi0 * inv_rescale_f(n0.x);
    float v0y = mdi0 * inv_rescale_f(n0.y);
    float v0w = mdi0 * inv_rescale_f(n0.w);
    float v1x = mdi1 * inv_rescale_f(n1.x);
    float v1y = mdi1 * inv_rescale_f(n1.y);
    float v1w = mdi1 * inv_rescale_f(n1.w);

    // ---- window neighbors via warp shuffles (no shared, no barrier) ----
    // A[t0+2],A[t0+3] live in lane+1; A[t0+4],A[t0+5] in lane+2.
    float A2x = __shfl_down_sync(0xffffffffu, a0x, 1);
    float A2y = __shfl_down_sync(0xffffffffu, a0y, 1);
    float A2w = __shfl_down_sync(0xffffffffu, a0w, 1);
    float A3x = __shfl_down_sync(0xffffffffu, a1x, 1);
    float A3y = __shfl_down_sync(0xffffffffu, a1y, 1);
    float A3w = __shfl_down_sync(0xffffffffu, a1w, 1);
    float A4x = __shfl_down_sync(0xffffffffu, a0x, 2);
    float A4y = __shfl_down_sync(0xffffffffu, a0y, 2);
    float A4w = __shfl_down_sync(0xffffffffu, a0w, 2);
    float A5x = __shfl_down_sync(0xffffffffu, a1x, 2);
    float A5y = __shfl_down_sync(0xffffffffu, a1y, 2);
    float A5w = __shfl_down_sync(0xffffffffu, a1w, 2);

    // warp-boundary lanes rebuild their out-of-warp A values from global
    if (lane >= 30) {
        if (lane == 31) {
            buildA(mask, done, logp, rw4, row, t0 + 2, A2x, A2y, A2w);
            buildA(mask, done, logp, rw4, row, t0 + 3, A3x, A3y, A3w);
        }
        buildA(mask, done, logp, rw4, row, t0 + 4, A4x, A4y, A4w);
        buildA(mask, done, logp, rw4, row, t0 + 5, A5x, A5y, A5w);
    }

    // rs1 = sum_{n=0..4} gamma^n A[t0+1+n]
    float rs1x = fmaf(GAMMA4, A5x, fmaf(GAMMA3, A4x, fmaf(GAMMA2, A3x, fmaf(GAMMA, A2x, a1x))));
    float rs1y = fmaf(GAMMA4, A5y, fmaf(GAMMA3, A4y, fmaf(GAMMA2, A3y, fmaf(GAMMA, A2y, a1y))));
    float rs1w = fmaf(GAMMA4, A5w, fmaf(GAMMA3, A4w, fmaf(GAMMA2, A3w, fmaf(GAMMA, A2w, a1w))));
    // rs0 = A[t0] + gamma*rs1 - gamma^5 * A[t0+5]
    float rs0x = fmaf(GAMMA, rs1x, fmaf(-GAMMA5, A5x, a0x));
    float rs0y = fmaf(GAMMA, rs1y, fmaf(-GAMMA5, A5y, a0y));
    float rs0w = fmaf(GAMMA, rs1w, fmaf(-GAMMA5, A5w, a0w));

    const float gi0 = expf((float)idx0 * LN_GAMMA);          // gamma^idx (absolute)
    const float gi1 = (idx1 == idx0) ? gi0 : gi0 * GAMMA;

    // Q_WEIGHTS = [1, 0.5, 0, 2]
    float e0x = c0.x - rescale_f(fmaf(gi0, v0x, rs0x));
    float e0y = c0.y - rescale_f(fmaf(gi0, v0y, rs0y));
    float e0w = c0.w - rescale_f(fmaf(gi0, v0w, rs0w));
    float e1x = c1.x - rescale_f(fmaf(gi1, v1x, rs1x));
    float e1y = c1.y - rescale_f(fmaf(gi1, v1y, rs1y));
    float e1w = c1.w - rescale_f(fmaf(gi1, v1w, rs1w));

    float4 o0, o1;
    o0.x = 0.5f  * m2.x * e0x * e0x;
    o0.y = 0.25f * m2.x * e0y * e0y;
    o0.z = 0.0f;
    o0.w = m2.x * e0w * e0w;
    o1.x = 0.5f  * m2.y * e1x * e1x;
    o1.y = 0.25f * m2.y * e1y * e1y;
    o1.z = 0.0f;
    o1.w = m2.y * e1w * e1w;

    ((float4*)out)[bt0]     = o0;
    ((float4*)out)[bt0 + 1] = o1;
}

extern "C" void kernel_launch(void* const* d_in, const int* in_sizes, int n_in,
                              void* d_out, int out_size)
{
    // metadata order: current_q_value, next_q_value, log_p, reward, is_done, mask
    const float* cq   = (const float*)d_in[0];
    const float* nq   = (const float*)d_in[1];
    const float* logp = (const float*)d_in[2];
    const float* rw   = (const float*)d_in[3];
    const float* done = (const float*)d_in[4];
    const float* mask = (const float*)d_in[5];
    float* out = (float*)d_out;

    int B = in_sizes[2] / T_DIM;   // log_p has B*T elements
    nstep_qloss_kernel<<<B, TPB>>>(cq, nq, logp, rw, done, mask, out);
}

// round 11
// speedup vs baseline: 1.0314x; 1.0010x over previous
#include <cuda_runtime.h>

#define T_DIM 512
#define TPB   256
#define N_STEPS 5

__device__ __forceinline__ float sqrt_approx(float x) {
    float r; asm("sqrt.approx.f32 %0, %1;" : "=f"(r) : "f"(x)); return r;
}
__device__ __forceinline__ float rcp_approx(float x) {
    float r; asm("rcp.approx.f32 %0, %1;" : "=f"(r) : "f"(x)); return r;
}

// sign(x)*(sqrt(|x|+1)-1) + EPS*x  — sqrt.approx is safe here: the
// subtraction only needs ABSOLUTE accuracy (~1e-7) vs O(1) residuals.
__device__ __forceinline__ float rescale_f(float x) {
    const float EPS = 1e-3f;
    float t = fabsf(x) + 1.0f;
    return fmaf(EPS, x, copysignf(sqrt_approx(t) - 1.0f, x));
}

// sign(x)*( ((sqrt(s)-1)/(2e))^2 - 1 ), s = 1+4e(|x|+1+e).
// Cancellation-stable identity: (sqrt(s)-1)/(2e) = 2(|x|+1+e)/(1+sqrt(s)),
// so approx sqrt/rcp error is NOT amplified by 1/(2e).
__device__ __forceinline__ float inv_rescale_f(float x) {
    const float EPS = 1e-3f;
    float a = fabsf(x) + (1.0f + EPS);
    float s = fmaf(4.0f * EPS, a, 1.0f);
    float r = (2.0f * a) * rcp_approx(1.0f + sqrt_approx(s));
    return copysignf(fmaf(r, r, -1.0f), x);
}

__global__ __launch_bounds__(TPB)
void nstep_qloss_kernel(const float* __restrict__ cq,
                        const float* __restrict__ nq,
                        const float* __restrict__ logp,
                        const float* __restrict__ rw,
                        const float* __restrict__ done,
                        const float* __restrict__ mask,
                        float* __restrict__ out)
{
    // Only A is staged in shared: A[t] = m*reward + gamma*inv_qw*(md*logp/3)
    __shared__ float4 s_A[T_DIM + N_STEPS - 1];

    const float GAMMA  = 0.997f;
    const float GAMMA2 = 0.997f * 0.997f;
    const float GAMMA3 = GAMMA2 * 0.997f;
    const float GAMMA4 = GAMMA3 * 0.997f;
    const float GAMMA5 = GAMMA4 * 0.997f;
    const float LN_GAMMA = -0.003004509021390342f; // ln(0.997)

    const int b   = blockIdx.x;
    const int l   = threadIdx.x;
    const int t0  = 2 * l;
    const int row = b * T_DIM;
    const int bt0 = row + t0;              // float4-unit index for Q=4 streams
    const int sc  = b * TPB + l;           // float2-unit index for scalar streams

    // gathered indices (clamped at row end)
    const int idx0 = min(T_DIM - 1, t0 + 4);
    const int idx1 = min(T_DIM - 1, t0 + 5);

    // ---- hoisted global loads (max MLP) ----
    float4 c0 = ((const float4*)cq)[bt0];
    float4 c1 = ((const float4*)cq)[bt0 + 1];
    float2 m2 = ((const float2*)mask)[sc];
    float2 d2 = ((const float2*)done)[sc];
    float2 p2 = ((const float2*)logp)[sc];
    float4 r0 = ((const float4*)rw)[bt0];
    float4 r1 = ((const float4*)rw)[bt0 + 1];
    // gathered scalars: (mask,done) at t0+4,t0+5 = one float2 each when in range
    float mi0, mi1, di0, di1;
    if (l <= TPB - 3) {                     // t0+5 <= 511
        float2 mg = ((const float2*)mask)[sc + 2];
        float2 dg = ((const float2*)done)[sc + 2];
        mi0 = mg.x; mi1 = mg.y;
        di0 = dg.x; di1 = dg.y;
    } else {                                // last 2 threads clamp to 511
        mi0 = mi1 = mask[row + T_DIM - 1];
        di0 = di1 = done[row + T_DIM - 1];
    }
    float4 n0 = ((const float4*)nq)[row + idx0];
    float4 n1 = ((const float4*)nq)[row + idx1];

    const float md0 = m2.x * (1.0f - d2.x);
    const float md1 = m2.y * (1.0f - d2.y);
    const float lb0 = (GAMMA / 3.0f) * md0 * p2.x;   // per-lane *inv_qw = [1,2,-,0.5]
    const float lb1 = (GAMMA / 3.0f) * md1 * p2.y;

    float4 a0, a1;
    a0.x = fmaf(m2.x, r0.x, lb0);
    a0.y = fmaf(m2.x, r0.y, 2.0f * lb0);
    a0.z = 0.0f;
    a0.w = fmaf(m2.x, r0.w, 0.5f * lb0);
    a1.x = fmaf(m2.y, r1.x, lb1);
    a1.y = fmaf(m2.y, r1.y, 2.0f * lb1);
    a1.z = 0.0f;
    a1.w = fmaf(m2.y, r1.w, 0.5f * lb1);
    s_A[t0]     = a0;
    s_A[t0 + 1] = a1;
    if (l < 2) {
        s_A[T_DIM + 2 * l]     = make_float4(0.f, 0.f, 0.f, 0.f);
        s_A[T_DIM + 2 * l + 1] = make_float4(0.f, 0.f, 0.f, 0.f);
    }

    // gathered next-q term computed directly in registers
    const float mdi0 = mi0 * (1.0f - di0);
    const float mdi1 = mi1 * (1.0f - di1);
    float v0x = mdi0 * inv_rescale_f(n0.x);
    float v0y = mdi0 * inv_rescale_f(n0.y);
    float v0w = mdi0 * inv_rescale_f(n0.w);
    float v1x = mdi1 * inv_rescale_f(n1.x);
    float v1y = mdi1 * inv_rescale_f(n1.y);
    float v1w = mdi1 * inv_rescale_f(n1.w);

    __syncthreads();

    // window values A[t0+2 .. t0+5] from shared; A[t0], A[t0+1] in regs
    float4 A2 = s_A[t0 + 2];
    float4 A3 = s_A[t0 + 3];
    float4 A4 = s_A[t0 + 4];
    float4 A5 = s_A[t0 + 5];

    // rs1 = sum_{n=0..4} gamma^n A[t0+1+n]
    float rs1x = fmaf(GAMMA4, A5.x, fmaf(GAMMA3, A4.x, fmaf(GAMMA2, A3.x, fmaf(GAMMA, A2.x, a1.x))));
    float rs1y = fmaf(GAMMA4, A5.y, fmaf(GAMMA3, A4.y, fmaf(GAMMA2, A3.y, fmaf(GAMMA, A2.y, a1.y))));
    float rs1w = fmaf(GAMMA4, A5.w, fmaf(GAMMA3, A4.w, fmaf(GAMMA2, A3.w, fmaf(GAMMA, A2.w, a1.w))));
    // rs0 = A[t0] + gamma*rs1 - gamma^5 * A[t0+5]
    float rs0x = fmaf(GAMMA, rs1x, fmaf(-GAMMA5, A5.x, a0.x));
    float rs0y = fmaf(GAMMA, rs1y, fmaf(-GAMMA5, A5.y, a0.y));
    float rs0w = fmaf(GAMMA, rs1w, fmaf(-GAMMA5, A5.w, a0.w));

    const float gi0 = __expf((float)idx0 * LN_GAMMA);        // gamma^idx (absolute)
    const float gi1 = (idx1 == idx0) ? gi0 : gi0 * GAMMA;

    // Q_WEIGHTS = [1, 0.5, 0, 2]
    float e0x = c0.x - rescale_f(fmaf(gi0, v0x, rs0x));
    float e0y = c0.y - rescale_f(fmaf(gi0, v0y, rs0y));
    float e0w = c0.w - rescale_f(fmaf(gi0, v0w, rs0w));
    float e1x = c1.x - rescale_f(fmaf(gi1, v1x, rs1x));
    float e1y = c1.y - rescale_f(fmaf(gi1, v1y, rs1y));
    float e1w = c1.w - rescale_f(fmaf(gi1, v1w, rs1w));

    float4 o0, o1;
    o0.x = 0.5f  * m2.x * e0x * e0x;
    o0.y = 0.25f * m2.x * e0y * e0y;
    o0.z = 0.0f;
    o0.w = m2.x * e0w * e0w;
    o1.x = 0.5f  * m2.y * e1x * e1x;
    o1.y = 0.25f * m2.y * e1y * e1y;
    o1.z = 0.0f;
    o1.w = m2.y * e1w * e1w;

    ((float4*)out)[bt0]     = o0;
    ((float4*)out)[bt0 + 1] = o1;
}

extern "C" void kernel_launch(void* const* d_in, const int* in_sizes, int n_in,
                              void* d_out, int out_size)
{
    // metadata order: current_q_value, next_q_value, log_p, reward, is_done, mask
    const float* cq   = (const float*)d_in[0];
    const float* nq   = (const float*)d_in[1];
    const float* logp = (const float*)d_in[2];
    const float* rw   = (const float*)d_in[3];
    const float* done = (const float*)d_in[4];
    const float* mask = (const float*)d_in[5];
    float* out = (float*)d_out;

    int B = in_sizes[2] / T_DIM;   // log_p has B*T elements
    nstep_qloss_kernel<<<B, TPB>>>(cq, nq, logp, rw, done, mask, out);
}

// round 12
// speedup vs baseline: 1.0707x; 1.0381x over previous
#include <cuda_runtime.h>

#define T_DIM 512
#define TPB   256
#define N_STEPS 5

__device__ __forceinline__ float sqrt_approx(float x) {
    float r; asm("sqrt.approx.f32 %0, %1;" : "=f"(r) : "f"(x)); return r;
}
__device__ __forceinline__ float rcp_approx(float x) {
    float r; asm("rcp.approx.f32 %0, %1;" : "=f"(r) : "f"(x)); return r;
}

// sign(x)*(sqrt(|x|+1)-1) + EPS*x  — sqrt.approx is safe: the subtraction
// only needs ABSOLUTE accuracy (~1e-7) vs O(1) residuals.
__device__ __forceinline__ float rescale_f(float x) {
    const float EPS = 1e-3f;
    float t = fabsf(x) + 1.0f;
    return fmaf(EPS, x, copysignf(sqrt_approx(t) - 1.0f, x));
}

// sign(x)*( ((sqrt(s)-1)/(2e))^2 - 1 ), s = 1+4e(|x|+1+e).
// Cancellation-stable identity: (sqrt(s)-1)/(2e) = 2(|x|+1+e)/(1+sqrt(s)).
__device__ __forceinline__ float inv_rescale_f(float x) {
    const float EPS = 1e-3f;
    float a = fabsf(x) + (1.0f + EPS);
    float s = fmaf(4.0f * EPS, a, 1.0f);
    float r = (2.0f * a) * rcp_approx(1.0f + sqrt_approx(s));
    return copysignf(fmaf(r, r, -1.0f), x);
}

__global__ __launch_bounds__(TPB, 5)
void nstep_qloss_kernel(const float* __restrict__ cq,
                        const float* __restrict__ nq,
                        const float* __restrict__ logp,
                        const float* __restrict__ rw,
                        const float* __restrict__ done,
                        const float* __restrict__ mask,
                        float* __restrict__ out)
{
    // Only A is staged in shared: A[t] = m*reward + gamma*inv_qw*(md*logp/3)
    __shared__ float4 s_A[T_DIM + N_STEPS - 1];

    const float GAMMA  = 0.997f;
    const float GAMMA2 = 0.997f * 0.997f;
    const float GAMMA3 = GAMMA2 * 0.997f;
    const float GAMMA4 = GAMMA3 * 0.997f;
    const float GAMMA5 = GAMMA4 * 0.997f;
    const float LN_GAMMA = -0.003004509021390342f; // ln(0.997)

    const int b   = blockIdx.x;
    const int l   = threadIdx.x;
    const int t0  = 2 * l;
    const int row = b * T_DIM;
    const int bt0 = row + t0;              // float4-unit index for Q=4 streams
    const int sc  = b * TPB + l;           // float2-unit index for scalar streams

    // gathered indices (clamped at row end)
    const int idx0 = min(T_DIM - 1, t0 + 4);
    const int idx1 = min(T_DIM - 1, t0 + 5);

    // ---- hoisted global loads (max MLP) ----
    float4 c0 = ((const float4*)cq)[bt0];
    float4 c1 = ((const float4*)cq)[bt0 + 1];
    float2 m2 = ((const float2*)mask)[sc];
    float2 d2 = ((const float2*)done)[sc];
    float2 p2 = ((const float2*)logp)[sc];
    float4 r0 = ((const float4*)rw)[bt0];
    float4 r1 = ((const float4*)rw)[bt0 + 1];
    // gathered scalars: (mask,done) at t0+4,t0+5 = one float2 each when in range
    float mi0, mi1, di0, di1;
    if (l <= TPB - 3) {                     // t0+5 <= 511
        float2 mg = ((const float2*)mask)[sc + 2];
        float2 dg = ((const float2*)done)[sc + 2];
        mi0 = mg.x; mi1 = mg.y;
        di0 = dg.x; di1 = dg.y;
    } else {                                // last 2 threads clamp to 511
        mi0 = mi1 = mask[row + T_DIM - 1];
        di0 = di1 = done[row + T_DIM - 1];
    }
    float4 n0 = ((const float4*)nq)[row + idx0];
    float4 n1 = ((const float4*)nq)[row + idx1];

    const float md0 = m2.x * (1.0f - d2.x);
    const float md1 = m2.y * (1.0f - d2.y);
    const float lb0 = (GAMMA / 3.0f) * md0 * p2.x;   // per-lane *inv_qw = [1,2,-,0.5]
    const float lb1 = (GAMMA / 3.0f) * md1 * p2.y;

    float4 a0, a1;
    a0.x = fmaf(m2.x, r0.x, lb0);
    a0.y = fmaf(m2.x, r0.y, 2.0f * lb0);
    a0.z = 0.0f;
    a0.w = fmaf(m2.x, r0.w, 0.5f * lb0);
    a1.x = fmaf(m2.y, r1.x, lb1);
    a1.y = fmaf(m2.y, r1.y, 2.0f * lb1);
    a1.z = 0.0f;
    a1.w = fmaf(m2.y, r1.w, 0.5f * lb1);
    s_A[t0]     = a0;
    s_A[t0 + 1] = a1;
    if (l < 2) {
        s_A[T_DIM + 2 * l]     = make_float4(0.f, 0.f, 0.f, 0.f);
        s_A[T_DIM + 2 * l + 1] = make_float4(0.f, 0.f, 0.f, 0.f);
    }

    // gathered next-q term computed directly in registers
    const float mdi0 = mi0 * (1.0f - di0);
    const float mdi1 = mi1 * (1.0f - di1);
    float v0x = mdi0 * inv_rescale_f(n0.x);
    float v0y = mdi0 * inv_rescale_f(n0.y);
    float v0w = mdi0 * inv_rescale_f(n0.w);
    float v1x = mdi1 * inv_rescale_f(n1.x);
    float v1y = mdi1 * inv_rescale_f(n1.y);
    float v1w = mdi1 * inv_rescale_f(n1.w);

    __syncthreads();

    // window values A[t0+2 .. t0+5] from shared; A[t0], A[t0+1] in regs
    float4 A2 = s_A[t0 + 2];
    float4 A3 = s_A[t0 + 3];
    float4 A4 = s_A[t0 + 4];
    float4 A5 = s_A[t0 + 5];

    // rs1 = sum_{n=0..4} gamma^n A[t0+1+n]
    float rs1x = fmaf(GAMMA4, A5.x, fmaf(GAMMA3, A4.x, fmaf(GAMMA2, A3.x, fmaf(GAMMA, A2.x, a1.x))));
    float rs1y = fmaf(GAMMA4, A5.y, fmaf(GAMMA3, A4.y, fmaf(GAMMA2, A3.y, fmaf(GAMMA, A2.y, a1.y))));
    float rs1w = fmaf(GAMMA4, A5.w, fmaf(GAMMA3, A4.w, fmaf(GAMMA2, A3.w, fmaf(GAMMA, A2.w, a1.w))));
    // rs0 = A[t0] + gamma*rs1 - gamma^5 * A[t0+5]
    float rs0x = fmaf(GAMMA, rs1x, fmaf(-GAMMA5, A5.x, a0.x));
    float rs0y = fmaf(GAMMA, rs1y, fmaf(-GAMMA5, A5.y, a0.y));
    float rs0w = fmaf(GAMMA, rs1w, fmaf(-GAMMA5, A5.w, a0.w));

    const float gi0 = __expf((float)idx0 * LN_GAMMA);        // gamma^idx (absolute)
    const float gi1 = (idx1 == idx0) ? gi0 : gi0 * GAMMA;

    // Q_WEIGHTS = [1, 0.5, 0, 2]
    float e0x = c0.x - rescale_f(fmaf(gi0, v0x, rs0x));
    float e0y = c0.y - rescale_f(fmaf(gi0, v0y, rs0y));
    float e0w = c0.w - rescale_f(fmaf(gi0, v0w, rs0w));
    float e1x = c1.x - rescale_f(fmaf(gi1, v1x, rs1x));
    float e1y = c1.y - rescale_f(fmaf(gi1, v1y, rs1y));
    float e1w = c1.w - rescale_f(fmaf(gi1, v1w, rs1w));

    float4 o0, o1;
    o0.x = 0.5f  * m2.x * e0x * e0x;
    o0.y = 0.25f * m2.x * e0y * e0y;
    o0.z = 0.0f;
    o0.w = m2.x * e0w * e0w;
    o1.x = 0.5f  * m2.y * e1x * e1x;
    o1.y = 0.25f * m2.y * e1y * e1y;
    o1.z = 0.0f;
    o1.w = m2.y * e1w * e1w;

    ((float4*)out)[bt0]     = o0;
    ((float4*)out)[bt0 + 1] = o1;
}

extern "C" void kernel_launch(void* const* d_in, const int* in_sizes, int n_in,
                              void* d_out, int out_size)
{
    // metadata order: current_q_value, next_q_value, log_p, reward, is_done, mask
    const float* cq   = (const float*)d_in[0];
    const float* nq   = (const float*)d_in[1];
    const float* logp = (const float*)d_in[2];
    const float* rw   = (const float*)d_in[3];
    const float* done = (const float*)d_in[4];
    const float* mask = (const float*)d_in[5];
    float* out = (float*)d_out;

    int B = in_sizes[2] / T_DIM;   // log_p has B*T elements
    nstep_qloss_kernel<<<B, TPB>>>(cq, nq, logp, rw, done, mask, out);
}